// round 1
// baseline (speedup 1.0000x reference)
#include <cuda_runtime.h>

// ---------------- problem constants (fixed by the dataset) ----------------
#define N_NODES  50000
#define E_MAX    450000
#define NFEAT    512
#define NHID     64
#define NHEADS   8
#define NOUT     128
#define X2DIM    512   // NHEADS * NHID

// ---------------- device scratch (no allocations allowed) -----------------
__device__ float g_h_all[(size_t)N_NODES * X2DIM];   // layer-1 head features [N,512]
__device__ float g_x2  [(size_t)N_NODES * X2DIM];    // concat(elu(...))      [N,512]
__device__ float g_s1  [N_NODES * NHEADS];
__device__ float g_s2  [N_NODES * NHEADS];
__device__ float g_hmu [(size_t)N_NODES * NOUT];
__device__ float g_hlv [(size_t)N_NODES * NOUT];
__device__ float g_smu1[N_NODES], g_smu2[N_NODES], g_slv1[N_NODES], g_slv2[N_NODES];
__device__ int   g_rowptr[N_NODES + 1];
__device__ int   g_col [E_MAX];
__device__ int   g_cnt [N_NODES];
__device__ int   g_cursor[N_NODES];

// ---------------- CSR construction ----------------------------------------
__global__ void zero_kernel(int n) {
    int i = blockIdx.x * blockDim.x + threadIdx.x;
    if (i < n) { g_cnt[i] = 0; g_cursor[i] = 0; }
}

__global__ void hist_kernel(const int* __restrict__ ei, int E) {
    int e = blockIdx.x * blockDim.x + threadIdx.x;
    if (e < E) atomicAdd(&g_cnt[ei[e]], 1);
}

// single-block exclusive scan over g_cnt -> g_rowptr (n up to 50000)
__global__ void scan_kernel(int n) {
    __shared__ int sh[1024];
    __shared__ int carry;
    if (threadIdx.x == 0) carry = 0;
    __syncthreads();
    for (int base = 0; base < n; base += 1024) {
        int i = base + threadIdx.x;
        int v = (i < n) ? g_cnt[i] : 0;
        sh[threadIdx.x] = v;
        __syncthreads();
        for (int off = 1; off < 1024; off <<= 1) {
            int t = (threadIdx.x >= off) ? sh[threadIdx.x - off] : 0;
            __syncthreads();
            sh[threadIdx.x] += t;
            __syncthreads();
        }
        if (i < n) g_rowptr[i] = carry + sh[threadIdx.x] - v;   // exclusive
        __syncthreads();
        if (threadIdx.x == 0) carry += sh[1023];
        __syncthreads();
    }
    if (threadIdx.x == 0) g_rowptr[n] = carry;
}

__global__ void fill_kernel(const int* __restrict__ ei, int E) {
    int e = blockIdx.x * blockDim.x + threadIdx.x;
    if (e < E) {
        int s = ei[e];
        int d = ei[E + e];
        int p = atomicAdd(&g_cursor[s], 1);
        g_col[g_rowptr[s] + p] = d;
    }
}

// ---------------- fp32 tiled GEMM: C[M,N] = A[M,K] * B[K,N] ----------------
// BM=128 BN=64 BK=16, 256 threads, 8x4 per-thread tile.
// blockIdx.z selects B += z*strideBz, C += z*strideCz (for 8-head batched GEMM)
#define GBM 128
#define GBN 64
#define GBK 16

__global__ __launch_bounds__(256) void gemm_f32(
    const float* __restrict__ A, const float* __restrict__ B, float* __restrict__ C,
    int M, int N, int K, int ldb, int ldc, int strideBz, int strideCz)
{
    B += (size_t)blockIdx.z * strideBz;
    C += (size_t)blockIdx.z * strideCz;
    __shared__ float Ast[GBK][GBM + 4];   // transposed A tile, padded
    __shared__ float Bs [GBK][GBN];

    int tid = threadIdx.x;
    int tx = tid & 15, ty = tid >> 4;
    int m0 = blockIdx.x * GBM;
    int n0 = blockIdx.y * GBN;

    float acc[8][4];
#pragma unroll
    for (int i = 0; i < 8; i++)
#pragma unroll
        for (int j = 0; j < 4; j++) acc[i][j] = 0.f;

    int ar0 = tid >> 2;             // A-load: row within tile (+64 for 2nd)
    int ac0 = (tid & 3) * 4;        // A-load: k-subcolumn
    int br  = tid >> 4;             // B-load row
    int bc  = (tid & 15) * 4;       // B-load col

    for (int k0 = 0; k0 < K; k0 += GBK) {
#pragma unroll
        for (int s = 0; s < 2; s++) {
            int row = ar0 + s * 64;
            float4 v = make_float4(0.f, 0.f, 0.f, 0.f);
            if (m0 + row < M)
                v = *(const float4*)&A[(size_t)(m0 + row) * K + k0 + ac0];
            Ast[ac0 + 0][row] = v.x;
            Ast[ac0 + 1][row] = v.y;
            Ast[ac0 + 2][row] = v.z;
            Ast[ac0 + 3][row] = v.w;
        }
        *(float4*)&Bs[br][bc] =
            *(const float4*)&B[(size_t)(k0 + br) * ldb + n0 + bc];
        __syncthreads();
#pragma unroll
        for (int kk = 0; kk < GBK; kk++) {
            float4 a0 = *(const float4*)&Ast[kk][ty * 8];
            float4 a1 = *(const float4*)&Ast[kk][ty * 8 + 4];
            float4 b0 = *(const float4*)&Bs[kk][tx * 4];
            float a[8] = {a0.x, a0.y, a0.z, a0.w, a1.x, a1.y, a1.z, a1.w};
            float b[4] = {b0.x, b0.y, b0.z, b0.w};
#pragma unroll
            for (int i = 0; i < 8; i++)
#pragma unroll
                for (int j = 0; j < 4; j++)
                    acc[i][j] += a[i] * b[j];
        }
        __syncthreads();
    }
#pragma unroll
    for (int i = 0; i < 8; i++) {
        int row = m0 + ty * 8 + i;
        if (row < M) {
            float4 v = make_float4(acc[i][0], acc[i][1], acc[i][2], acc[i][3]);
            *(float4*)&C[(size_t)row * ldc + n0 + tx * 4] = v;
        }
    }
}

// ---------------- layer-1 attention scalars: s1/s2 [N,8] -------------------
__global__ __launch_bounds__(256) void scalars1_kernel(const float* __restrict__ As) {
    int n = blockIdx.x;
    int w = threadIdx.x >> 5, lane = threadIdx.x & 31;
    const float* hr = g_h_all + (size_t)n * X2DIM + w * NHID;
    float v0 = hr[lane], v1 = hr[lane + 32];
    const float* a = As + w * 2 * NHID;
    float d1 = v0 * a[lane]      + v1 * a[lane + 32];
    float d2 = v0 * a[64 + lane] + v1 * a[96 + lane];
#pragma unroll
    for (int o = 16; o; o >>= 1) {
        d1 += __shfl_down_sync(0xffffffffu, d1, o);
        d2 += __shfl_down_sync(0xffffffffu, d2, o);
    }
    if (lane == 0) { g_s1[n * 8 + w] = d1; g_s2[n * 8 + w] = d2; }
}

// ---------------- layer-1 edge aggregation + normalize + elu ---------------
__global__ __launch_bounds__(128) void agg1_kernel() {
    int n = blockIdx.x;
    int t = threadIdx.x;
    __shared__ float sh_s1[8];
    __shared__ float sh_den[8];
    __shared__ float sh_e[16 * 8];
    __shared__ int   sh_dst[16];
    if (t < 8) { sh_s1[t] = g_s1[n * 8 + t]; sh_den[t] = 0.f; }
    __syncthreads();
    int beg = g_rowptr[n], end = g_rowptr[n + 1];
    float acc0 = 0.f, acc1 = 0.f, acc2 = 0.f, acc3 = 0.f;
    int h0 = t >> 6;
    for (int eb = beg; eb < end; eb += 16) {
        int cnt = min(16, end - eb);
        if (t < cnt) sh_dst[t] = g_col[eb + t];
        __syncthreads();
        if (t < cnt * 8) {
            int le = t >> 3, h = t & 7;
            int d = sh_dst[le];
            float logit = sh_s1[h] + g_s2[d * 8 + h];
            float lr = logit > 0.f ? logit : 0.2f * logit;
            float e = __expf(-lr);
            sh_e[t] = e;
            atomicAdd(&sh_den[h], e);
        }
        __syncthreads();
        for (int le = 0; le < cnt; le++) {
            int d = sh_dst[le];
            const float* hr = g_h_all + (size_t)d * X2DIM;
            acc0 += sh_e[le * 8 + h0]     * hr[t];
            acc1 += sh_e[le * 8 + h0 + 2] * hr[t + 128];
            acc2 += sh_e[le * 8 + h0 + 4] * hr[t + 256];
            acc3 += sh_e[le * 8 + h0 + 6] * hr[t + 384];
        }
        __syncthreads();
    }
    float v0 = acc0 / sh_den[h0];
    float v1 = acc1 / sh_den[h0 + 2];
    float v2 = acc2 / sh_den[h0 + 4];
    float v3 = acc3 / sh_den[h0 + 6];
    float* xo = g_x2 + (size_t)n * X2DIM;
    xo[t      ] = v0 > 0.f ? v0 : expm1f(v0);
    xo[t + 128] = v1 > 0.f ? v1 : expm1f(v1);
    xo[t + 256] = v2 > 0.f ? v2 : expm1f(v2);
    xo[t + 384] = v3 > 0.f ? v3 : expm1f(v3);
}

// ---------------- layer-2 attention scalars --------------------------------
__global__ __launch_bounds__(128) void scalars2_kernel(
    const float* __restrict__ mua, const float* __restrict__ lva)
{
    int n = blockIdx.x, t = threadIdx.x;
    float hmu = g_hmu[(size_t)n * NOUT + t];
    float hlv = g_hlv[(size_t)n * NOUT + t];
    float p0 = hmu * mua[t];
    float p1 = hmu * mua[128 + t];
    float p2 = hlv * lva[t];
    float p3 = hlv * lva[128 + t];
#pragma unroll
    for (int o = 16; o; o >>= 1) {
        p0 += __shfl_down_sync(0xffffffffu, p0, o);
        p1 += __shfl_down_sync(0xffffffffu, p1, o);
        p2 += __shfl_down_sync(0xffffffffu, p2, o);
        p3 += __shfl_down_sync(0xffffffffu, p3, o);
    }
    __shared__ float red[4][4];
    int w = t >> 5, lane = t & 31;
    if (lane == 0) { red[w][0] = p0; red[w][1] = p1; red[w][2] = p2; red[w][3] = p3; }
    __syncthreads();
    if (t == 0) {
        g_smu1[n] = red[0][0] + red[1][0] + red[2][0] + red[3][0];
        g_smu2[n] = red[0][1] + red[1][1] + red[2][1] + red[3][1];
        g_slv1[n] = red[0][2] + red[1][2] + red[2][2] + red[3][2];
        g_slv2[n] = red[0][3] + red[1][3] + red[2][3] + red[3][3];
    }
}

// ---------------- layer-2 edge aggregation + reparameterize + output -------
__global__ __launch_bounds__(128) void agg2_kernel(
    const float* __restrict__ eps, float* __restrict__ out, int n_total)
{
    int n = blockIdx.x, t = threadIdx.x;
    __shared__ float sh_emu[32], sh_elv[32];
    __shared__ int   sh_dst[32];
    __shared__ float sden[2];
    if (t < 2) sden[t] = 0.f;
    float base_mu = g_smu1[n];
    float base_lv = g_slv1[n];
    __syncthreads();
    int beg = g_rowptr[n], end = g_rowptr[n + 1];
    float amu = 0.f, alv = 0.f;
    for (int eb = beg; eb < end; eb += 32) {
        int cnt = min(32, end - eb);
        if (t < cnt) {
            int d = g_col[eb + t];
            sh_dst[t] = d;
            float lmu = base_mu + g_smu2[d];
            float llv = base_lv + g_slv2[d];
            lmu = lmu > 0.f ? lmu : 0.2f * lmu;
            llv = llv > 0.f ? llv : 0.2f * llv;
            float emu = __expf(-lmu);
            float elv = __expf(-llv);
            sh_emu[t] = emu; sh_elv[t] = elv;
            atomicAdd(&sden[0], emu);
            atomicAdd(&sden[1], elv);
        }
        __syncthreads();
        for (int le = 0; le < cnt; le++) {
            int d = sh_dst[le];
            amu += sh_emu[le] * g_hmu[(size_t)d * NOUT + t];
            alv += sh_elv[le] * g_hlv[(size_t)d * NOUT + t];
        }
        __syncthreads();
    }
    float mu = amu / sden[0];
    float lv = alv / sden[1];
    float z  = eps[(size_t)n * NOUT + t] * expf(lv) + mu;
    size_t NO = (size_t)n_total * NOUT;
    out[(size_t)n * NOUT + t]            = z;
    out[NO + (size_t)n * NOUT + t]       = mu;
    out[2 * NO + (size_t)n * NOUT + t]   = lv;
}

// ---------------- host orchestration ---------------------------------------
extern "C" void kernel_launch(void* const* d_in, const int* in_sizes, int n_in,
                              void* d_out, int out_size)
{
    const float* x   = (const float*)d_in[0];
    const float* Ws  = (const float*)d_in[1];
    const float* As  = (const float*)d_in[2];
    const float* muW = (const float*)d_in[3];
    const float* mua = (const float*)d_in[4];
    const float* lvW = (const float*)d_in[5];
    const float* lva = (const float*)d_in[6];
    const float* eps = (const float*)d_in[7];
    const int*   ei  = (const int*)d_in[8];
    int E = in_sizes[8] / 2;
    int N = in_sizes[0] / NFEAT;
    float* out = (float*)d_out;

    float *p_hall, *p_x2, *p_hmu, *p_hlv;
    cudaGetSymbolAddress((void**)&p_hall, g_h_all);
    cudaGetSymbolAddress((void**)&p_x2,   g_x2);
    cudaGetSymbolAddress((void**)&p_hmu,  g_hmu);
    cudaGetSymbolAddress((void**)&p_hlv,  g_hlv);

    // CSR keyed on src
    zero_kernel<<<(N + 255) / 256, 256>>>(N);
    hist_kernel<<<(E + 255) / 256, 256>>>(ei, E);
    scan_kernel<<<1, 1024>>>(N);
    fill_kernel<<<(E + 255) / 256, 256>>>(ei, E);

    // layer-1: 8 head GEMMs fused into one batched launch
    dim3 g1((N + GBM - 1) / GBM, 1, NHEADS);
    gemm_f32<<<g1, 256>>>(x, Ws, p_hall, N, NHID, NFEAT, NHID, X2DIM,
                          NFEAT * NHID, NHID);
    scalars1_kernel<<<N, 256>>>(As);
    agg1_kernel<<<N, 128>>>();

    // layer-2: mu / logvar GEMMs
    dim3 g2((N + GBM - 1) / GBM, NOUT / GBN, 1);
    gemm_f32<<<g2, 256>>>(p_x2, muW, p_hmu, N, NOUT, X2DIM, NOUT, NOUT, 0, 0);
    gemm_f32<<<g2, 256>>>(p_x2, lvW, p_hlv, N, NOUT, X2DIM, NOUT, NOUT, 0, 0);
    scalars2_kernel<<<N, 128>>>(mua, lva);
    agg2_kernel<<<N, 128>>>(eps, out, N);
}

// round 3
// speedup vs baseline: 1.7912x; 1.7912x over previous
#include <cuda_runtime.h>
#include <cuda_bf16.h>
#include <cstdint>

// ---------------- problem constants ----------------
#define N_NODES  50000
#define E_MAX    450000
#define NFEAT    512
#define NHID     64
#define NHEADS   8
#define NOUT     128
#define X2DIM    512

// ---------------- device scratch ----------------
__device__ float g_h_all[(size_t)N_NODES * X2DIM];
__device__ float g_s1  [N_NODES * NHEADS];
__device__ float g_s2  [N_NODES * NHEADS];
__device__ float g_hmu [(size_t)N_NODES * NOUT];
__device__ float g_hlv [(size_t)N_NODES * NOUT];
__device__ float g_smu1[N_NODES], g_smu2[N_NODES], g_slv1[N_NODES], g_slv2[N_NODES];
__device__ int   g_rowptr[N_NODES + 1];
__device__ int   g_col [E_MAX];
__device__ int   g_cnt [N_NODES];
__device__ int   g_cursor[N_NODES];

// bf16 hi/lo split operands
__device__ __nv_bfloat16 g_xh [(size_t)N_NODES * NFEAT];
__device__ __nv_bfloat16 g_xl [(size_t)N_NODES * NFEAT];
__device__ __nv_bfloat16 g_x2h[(size_t)N_NODES * X2DIM];
__device__ __nv_bfloat16 g_x2l[(size_t)N_NODES * X2DIM];
__device__ __nv_bfloat16 g_bt1h[512 * 512], g_bt1l[512 * 512];   // Ws^T  [8*64,512]
__device__ __nv_bfloat16 g_btmh[128 * 512], g_btml[128 * 512];   // muW^T [128,512]
__device__ __nv_bfloat16 g_btlh[128 * 512], g_btll[128 * 512];   // lvW^T [128,512]

// ---------------- PTX helpers (all target-generic, sm_80+) ----------------
__device__ __forceinline__ unsigned smem_u32(const void* p) {
    unsigned r;
    asm("{ .reg .u64 t; cvta.to.shared.u64 t, %1; cvt.u32.u64 %0, t; }"
        : "=r"(r) : "l"(p));
    return r;
}
__device__ __forceinline__ void cp16(unsigned dst, const void* src, int srcsz) {
    asm volatile("cp.async.cg.shared.global [%0], [%1], 16, %2;"
                 :: "r"(dst), "l"(src), "r"(srcsz) : "memory");
}
__device__ __forceinline__ void cp_commit() {
    asm volatile("cp.async.commit_group;" ::: "memory");
}
__device__ __forceinline__ void ldsm4(unsigned& r0, unsigned& r1, unsigned& r2,
                                      unsigned& r3, unsigned a) {
    asm volatile("ldmatrix.sync.aligned.m8n8.x4.shared.b16 {%0,%1,%2,%3}, [%4];"
                 : "=r"(r0), "=r"(r1), "=r"(r2), "=r"(r3) : "r"(a));
}
__device__ __forceinline__ void mma16816(float* d, const unsigned* a, const unsigned* b) {
    asm volatile(
        "mma.sync.aligned.m16n8k16.row.col.f32.bf16.bf16.f32 "
        "{%0,%1,%2,%3}, {%4,%5,%6,%7}, {%8,%9}, {%0,%1,%2,%3};"
        : "+f"(d[0]), "+f"(d[1]), "+f"(d[2]), "+f"(d[3])
        : "r"(a[0]), "r"(a[1]), "r"(a[2]), "r"(a[3]), "r"(b[0]), "r"(b[1]));
}

// swizzled byte offset inside a tile whose rows are 64 bf16 = 128B
__device__ __forceinline__ unsigned aoff(int r, int k) {
    return (unsigned)((r << 7) + (((((k >> 3) ^ r) & 7)) << 4) + ((k & 7) << 1));
}

// ---------------- CSR construction ----------------
__global__ void zero_kernel(int n) {
    int i = blockIdx.x * blockDim.x + threadIdx.x;
    if (i < n) { g_cnt[i] = 0; g_cursor[i] = 0; }
}
__global__ void hist_kernel(const int* __restrict__ ei, int E) {
    int e = blockIdx.x * blockDim.x + threadIdx.x;
    if (e < E) atomicAdd(&g_cnt[ei[e]], 1);
}
__global__ void scan_kernel(int n) {
    __shared__ int sh[1024];
    __shared__ int carry;
    if (threadIdx.x == 0) carry = 0;
    __syncthreads();
    for (int base = 0; base < n; base += 1024) {
        int i = base + threadIdx.x;
        int v = (i < n) ? g_cnt[i] : 0;
        sh[threadIdx.x] = v;
        __syncthreads();
        for (int off = 1; off < 1024; off <<= 1) {
            int t = (threadIdx.x >= off) ? sh[threadIdx.x - off] : 0;
            __syncthreads();
            sh[threadIdx.x] += t;
            __syncthreads();
        }
        if (i < n) g_rowptr[i] = carry + sh[threadIdx.x] - v;
        __syncthreads();
        if (threadIdx.x == 0) carry += sh[1023];
        __syncthreads();
    }
    if (threadIdx.x == 0) g_rowptr[n] = carry;
}
__global__ void fill_kernel(const int* __restrict__ ei, int E) {
    int e = blockIdx.x * blockDim.x + threadIdx.x;
    if (e < E) {
        int s = ei[e];
        int d = ei[E + e];
        int p = atomicAdd(&g_cursor[s], 1);
        g_col[g_rowptr[s] + p] = d;
    }
}

// ---------------- fp32 -> bf16 hi/lo conversions ----------------
__global__ void convert_x_kernel(const float* __restrict__ x, int n4) {
    int i = blockIdx.x * blockDim.x + threadIdx.x;
    if (i >= n4) return;
    float4 v = ((const float4*)x)[i];
    __nv_bfloat16 h0 = __float2bfloat16_rn(v.x);
    __nv_bfloat16 h1 = __float2bfloat16_rn(v.y);
    __nv_bfloat16 h2 = __float2bfloat16_rn(v.z);
    __nv_bfloat16 h3 = __float2bfloat16_rn(v.w);
    __nv_bfloat16 l0 = __float2bfloat16_rn(v.x - __bfloat162float(h0));
    __nv_bfloat16 l1 = __float2bfloat16_rn(v.y - __bfloat162float(h1));
    __nv_bfloat16 l2 = __float2bfloat16_rn(v.z - __bfloat162float(h2));
    __nv_bfloat16 l3 = __float2bfloat16_rn(v.w - __bfloat162float(h3));
    ((__nv_bfloat162*)g_xh)[i * 2]     = __nv_bfloat162(h0, h1);
    ((__nv_bfloat162*)g_xh)[i * 2 + 1] = __nv_bfloat162(h2, h3);
    ((__nv_bfloat162*)g_xl)[i * 2]     = __nv_bfloat162(l0, l1);
    ((__nv_bfloat162*)g_xl)[i * 2 + 1] = __nv_bfloat162(l2, l3);
}

__global__ void convert_w_kernel(const float* __restrict__ Ws,
                                 const float* __restrict__ muW,
                                 const float* __restrict__ lvW) {
    int i = blockIdx.x * blockDim.x + threadIdx.x;
    float v;
    __nv_bfloat16 *ph, *pl;
    if (i < 512 * 512) {
        int row = i >> 9, k = i & 511;            // row = h*64 + n
        int h = row >> 6, n = row & 63;
        v = Ws[((size_t)h * 512 + k) * 64 + n];
        ph = g_bt1h + i; pl = g_bt1l + i;
    } else if (i < 512 * 512 + 128 * 512) {
        int j = i - 512 * 512;
        int n = j >> 9, k = j & 511;
        v = muW[(size_t)k * 128 + n];
        ph = g_btmh + j; pl = g_btml + j;
    } else if (i < 512 * 512 + 2 * 128 * 512) {
        int j = i - 512 * 512 - 128 * 512;
        int n = j >> 9, k = j & 511;
        v = lvW[(size_t)k * 128 + n];
        ph = g_btlh + j; pl = g_btll + j;
    } else return;
    __nv_bfloat16 hv = __float2bfloat16_rn(v);
    *ph = hv;
    *pl = __float2bfloat16_rn(v - __bfloat162float(hv));
}

// ---------------- HMMA bf16x3 GEMM -----------------------------------------
// C[m0..m0+127, y*64..y*64+63] = A[M,512] * Bt[y*64+n, 512]^T
// 3 passes fused per k16: Ah*Bh + Ah*Bl + Al*Bh, fp32 accum.
// SMEM stage (Kc=64): Ah 16K | Al 16K | Bh 8K | Bl 8K = 48KB, x2 stages = 96KB.
#define KC 64
#define STAGE 49152

__device__ __forceinline__ void load_chunk(
    unsigned st, const __nv_bfloat16* Ah, const __nv_bfloat16* Al,
    const __nv_bfloat16* Bh, const __nv_bfloat16* Bl,
    int m0, int k0, int M, int tid)
{
#pragma unroll
    for (int it = 0; it < 4; it++) {
        int idx = it * 256 + tid;
        int r = idx >> 3, c = idx & 7;
        int grow = m0 + r;
        int sz = (grow < M) ? 16 : 0;
        if (grow >= M) grow = M - 1;
        unsigned d = st + (unsigned)((r << 7) + (((c ^ (r & 7)) & 7) << 4));
        size_t go = (size_t)grow * 512 + k0 + c * 8;
        cp16(d,         Ah + go, sz);
        cp16(d + 16384, Al + go, sz);
    }
#pragma unroll
    for (int it = 0; it < 2; it++) {
        int idx = it * 256 + tid;
        int r = idx >> 3, c = idx & 7;
        unsigned d = st + 32768u + (unsigned)((r << 7) + (((c ^ (r & 7)) & 7) << 4));
        size_t go = (size_t)r * 512 + k0 + c * 8;
        cp16(d,        Bh + go, 16);
        cp16(d + 8192, Bl + go, 16);
    }
}

__global__ __launch_bounds__(256, 2) void gemm_tc(
    const __nv_bfloat16* __restrict__ Ah, const __nv_bfloat16* __restrict__ Al,
    const __nv_bfloat16* __restrict__ Bhg, const __nv_bfloat16* __restrict__ Blg,
    float* __restrict__ C, int M, int ldc)
{
    extern __shared__ char smem[];
    const unsigned sbase = smem_u32(smem);
    const int tid = threadIdx.x, lane = tid & 31, wid = tid >> 5;
    const int m0 = blockIdx.x * 128;
    const __nv_bfloat16* Bh = Bhg + (size_t)blockIdx.y * 64 * 512;
    const __nv_bfloat16* Bl = Blg + (size_t)blockIdx.y * 64 * 512;
    C += blockIdx.y * 64;
    const int wm = (wid & 3) * 32, wn = (wid >> 2) * 32;

    float acc[2][4][4];
#pragma unroll
    for (int i = 0; i < 2; i++)
#pragma unroll
        for (int j = 0; j < 4; j++)
#pragma unroll
            for (int q = 0; q < 4; q++) acc[i][j][q] = 0.f;

    load_chunk(sbase, Ah, Al, Bh, Bl, m0, 0, M, tid);
    cp_commit();

    for (int kc = 0; kc < 8; kc++) {
        if (kc < 7) {
            load_chunk(sbase + ((kc + 1) & 1) * STAGE, Ah, Al, Bh, Bl,
                       m0, (kc + 1) * KC, M, tid);
            cp_commit();
            asm volatile("cp.async.wait_group 1;" ::: "memory");
        } else {
            asm volatile("cp.async.wait_group 0;" ::: "memory");
        }
        __syncthreads();
        const unsigned st = sbase + (kc & 1) * STAGE;
#pragma unroll
        for (int kk = 0; kk < 4; kk++) {
            const int k = kk * 16;
            // A fragment addresses (rows 128B wide, swizzled)
            int ar = lane & 15;
            int ac = k + ((lane >> 4) << 3);
            unsigned ah[2][4], al[2][4];
            ldsm4(ah[0][0], ah[0][1], ah[0][2], ah[0][3], st + aoff(wm + ar, ac));
            ldsm4(ah[1][0], ah[1][1], ah[1][2], ah[1][3], st + aoff(wm + 16 + ar, ac));
            ldsm4(al[0][0], al[0][1], al[0][2], al[0][3], st + 16384 + aoff(wm + ar, ac));
            ldsm4(al[1][0], al[1][1], al[1][2], al[1][3], st + 16384 + aoff(wm + 16 + ar, ac));
            // B fragments
            int br = (lane & 7) + ((lane >> 4) << 3);
            int bc = k + (((lane >> 3) & 1) << 3);
            unsigned bh[4][2], bl[4][2];
            ldsm4(bh[0][0], bh[0][1], bh[1][0], bh[1][1], st + 32768 + aoff(wn + br, bc));
            ldsm4(bh[2][0], bh[2][1], bh[3][0], bh[3][1], st + 32768 + aoff(wn + 16 + br, bc));
            ldsm4(bl[0][0], bl[0][1], bl[1][0], bl[1][1], st + 40960 + aoff(wn + br, bc));
            ldsm4(bl[2][0], bl[2][1], bl[3][0], bl[3][1], st + 40960 + aoff(wn + 16 + br, bc));
#pragma unroll
            for (int mt = 0; mt < 2; mt++)
#pragma unroll
                for (int nt = 0; nt < 4; nt++) {
                    mma16816(acc[mt][nt], ah[mt], bh[nt]);
                    mma16816(acc[mt][nt], ah[mt], bl[nt]);
                    mma16816(acc[mt][nt], al[mt], bh[nt]);
                }
        }
        __syncthreads();
    }

    // store C (fragment: c0,c1 -> row g, cols 2c; c2,c3 -> row g+8)
#pragma unroll
    for (int mt = 0; mt < 2; mt++) {
        int r0 = m0 + wm + mt * 16 + (lane >> 2);
#pragma unroll
        for (int nt = 0; nt < 4; nt++) {
            int c0 = wn + nt * 8 + (lane & 3) * 2;
            if (r0 < M)
                *(float2*)&C[(size_t)r0 * ldc + c0] =
                    make_float2(acc[mt][nt][0], acc[mt][nt][1]);
            if (r0 + 8 < M)
                *(float2*)&C[(size_t)(r0 + 8) * ldc + c0] =
                    make_float2(acc[mt][nt][2], acc[mt][nt][3]);
        }
    }
}

// ---------------- layer-1 attention scalars ----------------
__global__ __launch_bounds__(256) void scalars1_kernel(const float* __restrict__ As) {
    int n = blockIdx.x;
    int w = threadIdx.x >> 5, lane = threadIdx.x & 31;
    const float* hr = g_h_all + (size_t)n * X2DIM + w * NHID;
    float v0 = hr[lane], v1 = hr[lane + 32];
    const float* a = As + w * 2 * NHID;
    float d1 = v0 * a[lane]      + v1 * a[lane + 32];
    float d2 = v0 * a[64 + lane] + v1 * a[96 + lane];
#pragma unroll
    for (int o = 16; o; o >>= 1) {
        d1 += __shfl_down_sync(0xffffffffu, d1, o);
        d2 += __shfl_down_sync(0xffffffffu, d2, o);
    }
    if (lane == 0) { g_s1[n * 8 + w] = d1; g_s2[n * 8 + w] = d2; }
}

// ---------------- layer-1 edge aggregation + normalize + elu + bf16 split --
__global__ __launch_bounds__(128) void agg1_kernel() {
    int n = blockIdx.x;
    int t = threadIdx.x;
    __shared__ float sh_s1[8];
    __shared__ float sh_den[8];
    __shared__ float sh_e[16 * 8];
    __shared__ int   sh_dst[16];
    if (t < 8) { sh_s1[t] = g_s1[n * 8 + t]; sh_den[t] = 0.f; }
    __syncthreads();
    int beg = g_rowptr[n], end = g_rowptr[n + 1];
    float acc0 = 0.f, acc1 = 0.f, acc2 = 0.f, acc3 = 0.f;
    int h0 = t >> 6;
    for (int eb = beg; eb < end; eb += 16) {
        int cnt = min(16, end - eb);
        if (t < cnt) sh_dst[t] = g_col[eb + t];
        __syncthreads();
        if (t < cnt * 8) {
            int le = t >> 3, h = t & 7;
            int d = sh_dst[le];
            float logit = sh_s1[h] + g_s2[d * 8 + h];
            float lr = logit > 0.f ? logit : 0.2f * logit;
            float e = __expf(-lr);
            sh_e[t] = e;
            atomicAdd(&sh_den[h], e);
        }
        __syncthreads();
        for (int le = 0; le < cnt; le++) {
            int d = sh_dst[le];
            const float* hr = g_h_all + (size_t)d * X2DIM;
            acc0 += sh_e[le * 8 + h0]     * hr[t];
            acc1 += sh_e[le * 8 + h0 + 2] * hr[t + 128];
            acc2 += sh_e[le * 8 + h0 + 4] * hr[t + 256];
            acc3 += sh_e[le * 8 + h0 + 6] * hr[t + 384];
        }
        __syncthreads();
    }
    float v0 = acc0 / sh_den[h0];
    float v1 = acc1 / sh_den[h0 + 2];
    float v2 = acc2 / sh_den[h0 + 4];
    float v3 = acc3 / sh_den[h0 + 6];
    v0 = v0 > 0.f ? v0 : expm1f(v0);
    v1 = v1 > 0.f ? v1 : expm1f(v1);
    v2 = v2 > 0.f ? v2 : expm1f(v2);
    v3 = v3 > 0.f ? v3 : expm1f(v3);
    size_t o = (size_t)n * X2DIM + t;
    __nv_bfloat16 h;
    h = __float2bfloat16_rn(v0); g_x2h[o      ] = h; g_x2l[o      ] = __float2bfloat16_rn(v0 - __bfloat162float(h));
    h = __float2bfloat16_rn(v1); g_x2h[o + 128] = h; g_x2l[o + 128] = __float2bfloat16_rn(v1 - __bfloat162float(h));
    h = __float2bfloat16_rn(v2); g_x2h[o + 256] = h; g_x2l[o + 256] = __float2bfloat16_rn(v2 - __bfloat162float(h));
    h = __float2bfloat16_rn(v3); g_x2h[o + 384] = h; g_x2l[o + 384] = __float2bfloat16_rn(v3 - __bfloat162float(h));
}

// ---------------- layer-2 attention scalars ----------------
__global__ __launch_bounds__(128) void scalars2_kernel(
    const float* __restrict__ mua, const float* __restrict__ lva)
{
    int n = blockIdx.x, t = threadIdx.x;
    float hmu = g_hmu[(size_t)n * NOUT + t];
    float hlv = g_hlv[(size_t)n * NOUT + t];
    float p0 = hmu * mua[t];
    float p1 = hmu * mua[128 + t];
    float p2 = hlv * lva[t];
    float p3 = hlv * lva[128 + t];
#pragma unroll
    for (int o = 16; o; o >>= 1) {
        p0 += __shfl_down_sync(0xffffffffu, p0, o);
        p1 += __shfl_down_sync(0xffffffffu, p1, o);
        p2 += __shfl_down_sync(0xffffffffu, p2, o);
        p3 += __shfl_down_sync(0xffffffffu, p3, o);
    }
    __shared__ float red[4][4];
    int w = t >> 5, lane = t & 31;
    if (lane == 0) { red[w][0] = p0; red[w][1] = p1; red[w][2] = p2; red[w][3] = p3; }
    __syncthreads();
    if (t == 0) {
        g_smu1[n] = red[0][0] + red[1][0] + red[2][0] + red[3][0];
        g_smu2[n] = red[0][1] + red[1][1] + red[2][1] + red[3][1];
        g_slv1[n] = red[0][2] + red[1][2] + red[2][2] + red[3][2];
        g_slv2[n] = red[0][3] + red[1][3] + red[2][3] + red[3][3];
    }
}

// ---------------- layer-2 edge aggregation + reparameterize ----------------
__global__ __launch_bounds__(128) void agg2_kernel(
    const float* __restrict__ eps, float* __restrict__ out, int n_total)
{
    int n = blockIdx.x, t = threadIdx.x;
    __shared__ float sh_emu[32], sh_elv[32];
    __shared__ int   sh_dst[32];
    __shared__ float sden[2];
    if (t < 2) sden[t] = 0.f;
    float base_mu = g_smu1[n];
    float base_lv = g_slv1[n];
    __syncthreads();
    int beg = g_rowptr[n], end = g_rowptr[n + 1];
    float amu = 0.f, alv = 0.f;
    for (int eb = beg; eb < end; eb += 32) {
        int cnt = min(32, end - eb);
        if (t < cnt) {
            int d = g_col[eb + t];
            sh_dst[t] = d;
            float lmu = base_mu + g_smu2[d];
            float llv = base_lv + g_slv2[d];
            lmu = lmu > 0.f ? lmu : 0.2f * lmu;
            llv = llv > 0.f ? llv : 0.2f * llv;
            float emu = __expf(-lmu);
            float elv = __expf(-llv);
            sh_emu[t] = emu; sh_elv[t] = elv;
            atomicAdd(&sden[0], emu);
            atomicAdd(&sden[1], elv);
        }
        __syncthreads();
        for (int le = 0; le < cnt; le++) {
            int d = sh_dst[le];
            amu += sh_emu[le] * g_hmu[(size_t)d * NOUT + t];
            alv += sh_elv[le] * g_hlv[(size_t)d * NOUT + t];
        }
        __syncthreads();
    }
    float mu = amu / sden[0];
    float lv = alv / sden[1];
    float z  = eps[(size_t)n * NOUT + t] * expf(lv) + mu;
    size_t NO = (size_t)n_total * NOUT;
    out[(size_t)n * NOUT + t]          = z;
    out[NO + (size_t)n * NOUT + t]     = mu;
    out[2 * NO + (size_t)n * NOUT + t] = lv;
}

// ---------------- host orchestration ----------------
extern "C" void kernel_launch(void* const* d_in, const int* in_sizes, int n_in,
                              void* d_out, int out_size)
{
    const float* x   = (const float*)d_in[0];
    const float* Ws  = (const float*)d_in[1];
    const float* As  = (const float*)d_in[2];
    const float* muW = (const float*)d_in[3];
    const float* mua = (const float*)d_in[4];
    const float* lvW = (const float*)d_in[5];
    const float* lva = (const float*)d_in[6];
    const float* eps = (const float*)d_in[7];
    const int*   ei  = (const int*)d_in[8];
    int E = in_sizes[8] / 2;
    int N = in_sizes[0] / NFEAT;
    float* out = (float*)d_out;

    float *p_hall, *p_hmu, *p_hlv;
    __nv_bfloat16 *p_xh, *p_xl, *p_x2h, *p_x2l;
    __nv_bfloat16 *p_bt1h, *p_bt1l, *p_btmh, *p_btml, *p_btlh, *p_btll;
    cudaGetSymbolAddress((void**)&p_hall, g_h_all);
    cudaGetSymbolAddress((void**)&p_hmu,  g_hmu);
    cudaGetSymbolAddress((void**)&p_hlv,  g_hlv);
    cudaGetSymbolAddress((void**)&p_xh,   g_xh);
    cudaGetSymbolAddress((void**)&p_xl,   g_xl);
    cudaGetSymbolAddress((void**)&p_x2h,  g_x2h);
    cudaGetSymbolAddress((void**)&p_x2l,  g_x2l);
    cudaGetSymbolAddress((void**)&p_bt1h, g_bt1h);
    cudaGetSymbolAddress((void**)&p_bt1l, g_bt1l);
    cudaGetSymbolAddress((void**)&p_btmh, g_btmh);
    cudaGetSymbolAddress((void**)&p_btml, g_btml);
    cudaGetSymbolAddress((void**)&p_btlh, g_btlh);
    cudaGetSymbolAddress((void**)&p_btll, g_btll);

    cudaFuncSetAttribute(gemm_tc, cudaFuncAttributeMaxDynamicSharedMemorySize, 2 * STAGE);

    // CSR keyed on src
    zero_kernel<<<(N + 255) / 256, 256>>>(N);
    hist_kernel<<<(E + 255) / 256, 256>>>(ei, E);
    scan_kernel<<<1, 1024>>>(N);
    fill_kernel<<<(E + 255) / 256, 256>>>(ei, E);

    // operand conversion
    convert_x_kernel<<<(N * NFEAT / 4 + 255) / 256, 256>>>(x, N * NFEAT / 4);
    convert_w_kernel<<<(512 * 512 + 2 * 128 * 512 + 255) / 256, 256>>>(Ws, muW, lvW);

    int mtiles = (N + 127) / 128;
    // layer-1: 8 heads; head h -> C cols h*64 of g_h_all [N,512]
    gemm_tc<<<dim3(mtiles, NHEADS), 256, 2 * STAGE>>>(p_xh, p_xl, p_bt1h, p_bt1l,
                                                      p_hall, N, X2DIM);
    scalars1_kernel<<<N, 256>>>(As);
    agg1_kernel<<<N, 128>>>();

    // layer-2: mu / logvar GEMMs, C [N,128], 2 n-tiles each
    gemm_tc<<<dim3(mtiles, 2), 256, 2 * STAGE>>>(p_x2h, p_x2l, p_btmh, p_btml,
                                                 p_hmu, N, NOUT);
    gemm_tc<<<dim3(mtiles, 2), 256, 2 * STAGE>>>(p_x2h, p_x2l, p_btlh, p_btll,
                                                 p_hlv, N, NOUT);
    scalars2_kernel<<<N, 128>>>(mua, lva);
    agg2_kernel<<<N, 128>>>(eps, out, N);
}

// round 4
// speedup vs baseline: 1.8313x; 1.0224x over previous
#include <cuda_runtime.h>
#include <cuda_bf16.h>
#include <cstdint>

// ---------------- problem constants ----------------
#define N_NODES  50000
#define E_MAX    450000
#define NFEAT    512
#define NHID     64
#define NHEADS   8
#define NOUT     128
#define X2DIM    512

// ---------------- device scratch ----------------
__device__ float g_h_all[(size_t)N_NODES * X2DIM];
__device__ float g_s1  [N_NODES * NHEADS];
__device__ float g_s2  [N_NODES * NHEADS];
__device__ float g_hml [(size_t)N_NODES * 256];   // [:,0:128]=h_mu, [:,128:256]=h_lv
__device__ float g_smu1[N_NODES], g_smu2[N_NODES], g_slv1[N_NODES], g_slv2[N_NODES];
__device__ int   g_rowptr[N_NODES + 1];
__device__ int   g_col [E_MAX];
__device__ int   g_cnt [N_NODES];
__device__ int   g_cursor[N_NODES];

// bf16 hi/lo split operands
__device__ __nv_bfloat16 g_xh [(size_t)N_NODES * NFEAT];
__device__ __nv_bfloat16 g_xl [(size_t)N_NODES * NFEAT];
__device__ __nv_bfloat16 g_x2h[(size_t)N_NODES * X2DIM];
__device__ __nv_bfloat16 g_x2l[(size_t)N_NODES * X2DIM];
__device__ __nv_bfloat16 g_bt1h[512 * 512], g_bt1l[512 * 512];   // Ws^T   [512,512]
__device__ __nv_bfloat16 g_bt2h[256 * 512], g_bt2l[256 * 512];   // [muW;lvW]^T [256,512]

// ---------------- PTX helpers (target-generic, sm_80+) ----------------
__device__ __forceinline__ unsigned smem_u32(const void* p) {
    unsigned r;
    asm("{ .reg .u64 t; cvta.to.shared.u64 t, %1; cvt.u32.u64 %0, t; }"
        : "=r"(r) : "l"(p));
    return r;
}
__device__ __forceinline__ void cp16(unsigned dst, const void* src, int srcsz) {
    asm volatile("cp.async.cg.shared.global [%0], [%1], 16, %2;"
                 :: "r"(dst), "l"(src), "r"(srcsz) : "memory");
}
__device__ __forceinline__ void cp_commit() {
    asm volatile("cp.async.commit_group;" ::: "memory");
}
__device__ __forceinline__ void ldsm4(unsigned& r0, unsigned& r1, unsigned& r2,
                                      unsigned& r3, unsigned a) {
    asm volatile("ldmatrix.sync.aligned.m8n8.x4.shared.b16 {%0,%1,%2,%3}, [%4];"
                 : "=r"(r0), "=r"(r1), "=r"(r2), "=r"(r3) : "r"(a));
}
__device__ __forceinline__ void mma16816(float* d, const unsigned* a, const unsigned* b) {
    asm volatile(
        "mma.sync.aligned.m16n8k16.row.col.f32.bf16.bf16.f32 "
        "{%0,%1,%2,%3}, {%4,%5,%6,%7}, {%8,%9}, {%0,%1,%2,%3};"
        : "+f"(d[0]), "+f"(d[1]), "+f"(d[2]), "+f"(d[3])
        : "r"(a[0]), "r"(a[1]), "r"(a[2]), "r"(a[3]), "r"(b[0]), "r"(b[1]));
}
// swizzled byte offset inside a tile whose rows are 64 bf16 = 128B
__device__ __forceinline__ unsigned aoff(int r, int k) {
    return (unsigned)((r << 7) + (((((k >> 3) ^ r) & 7)) << 4) + ((k & 7) << 1));
}

// ---------------- CSR construction ----------------
__global__ void zero_kernel(int n) {
    int i = blockIdx.x * blockDim.x + threadIdx.x;
    if (i < n) { g_cnt[i] = 0; g_cursor[i] = 0; }
}
__global__ void hist_kernel(const int* __restrict__ ei, int E) {
    int e = blockIdx.x * blockDim.x + threadIdx.x;
    if (e < E) atomicAdd(&g_cnt[ei[e]], 1);
}
__global__ void scan_kernel(int n) {
    __shared__ int sh[1024];
    __shared__ int carry;
    if (threadIdx.x == 0) carry = 0;
    __syncthreads();
    for (int base = 0; base < n; base += 1024) {
        int i = base + threadIdx.x;
        int v = (i < n) ? g_cnt[i] : 0;
        sh[threadIdx.x] = v;
        __syncthreads();
        for (int off = 1; off < 1024; off <<= 1) {
            int t = (threadIdx.x >= off) ? sh[threadIdx.x - off] : 0;
            __syncthreads();
            sh[threadIdx.x] += t;
            __syncthreads();
        }
        if (i < n) g_rowptr[i] = carry + sh[threadIdx.x] - v;
        __syncthreads();
        if (threadIdx.x == 0) carry += sh[1023];
        __syncthreads();
    }
    if (threadIdx.x == 0) g_rowptr[n] = carry;
}
__global__ void fill_kernel(const int* __restrict__ ei, int E) {
    int e = blockIdx.x * blockDim.x + threadIdx.x;
    if (e < E) {
        int s = ei[e];
        int d = ei[E + e];
        int p = atomicAdd(&g_cursor[s], 1);
        g_col[g_rowptr[s] + p] = d;
    }
}

// ---------------- fp32 -> bf16 hi/lo conversions ----------------
__global__ void convert_x_kernel(const float* __restrict__ x, int n4) {
    int i = blockIdx.x * blockDim.x + threadIdx.x;
    if (i >= n4) return;
    float4 v = ((const float4*)x)[i];
    __nv_bfloat16 h0 = __float2bfloat16_rn(v.x);
    __nv_bfloat16 h1 = __float2bfloat16_rn(v.y);
    __nv_bfloat16 h2 = __float2bfloat16_rn(v.z);
    __nv_bfloat16 h3 = __float2bfloat16_rn(v.w);
    __nv_bfloat16 l0 = __float2bfloat16_rn(v.x - __bfloat162float(h0));
    __nv_bfloat16 l1 = __float2bfloat16_rn(v.y - __bfloat162float(h1));
    __nv_bfloat16 l2 = __float2bfloat16_rn(v.z - __bfloat162float(h2));
    __nv_bfloat16 l3 = __float2bfloat16_rn(v.w - __bfloat162float(h3));
    ((__nv_bfloat162*)g_xh)[i * 2]     = __nv_bfloat162(h0, h1);
    ((__nv_bfloat162*)g_xh)[i * 2 + 1] = __nv_bfloat162(h2, h3);
    ((__nv_bfloat162*)g_xl)[i * 2]     = __nv_bfloat162(l0, l1);
    ((__nv_bfloat162*)g_xl)[i * 2 + 1] = __nv_bfloat162(l2, l3);
}

__global__ void convert_w_kernel(const float* __restrict__ Ws,
                                 const float* __restrict__ muW,
                                 const float* __restrict__ lvW) {
    int i = blockIdx.x * blockDim.x + threadIdx.x;
    float v;
    __nv_bfloat16 *ph, *pl;
    if (i < 512 * 512) {
        int row = i >> 9, k = i & 511;            // row = h*64 + n
        int h = row >> 6, n = row & 63;
        v = Ws[((size_t)h * 512 + k) * 64 + n];
        ph = g_bt1h + i; pl = g_bt1l + i;
    } else if (i < 512 * 512 + 256 * 512) {
        int j = i - 512 * 512;
        int n = j >> 9, k = j & 511;
        v = (n < 128) ? muW[(size_t)k * 128 + n]
                      : lvW[(size_t)k * 128 + (n - 128)];
        ph = g_bt2h + j; pl = g_bt2l + j;
    } else return;
    __nv_bfloat16 hv = __float2bfloat16_rn(v);
    *ph = hv;
    *pl = __float2bfloat16_rn(v - __bfloat162float(hv));
}

// ---------------- HMMA bf16x3 GEMM, 128x128 tile ---------------------------
// C[m0:+128, nb:+128] = A[M,512] * Bt[nb:+128, 512]^T (3 passes: hh+hl+lh)
// SMEM stage (Kc=64): Ah 16K | Al 16K | Bh 16K | Bl 16K = 64KB, x2 = 128KB.
#define KC 64
#define STAGE 65536

__device__ __forceinline__ void load_chunk(
    unsigned st, const __nv_bfloat16* Ah, const __nv_bfloat16* Al,
    const __nv_bfloat16* Bh, const __nv_bfloat16* Bl,
    int m0, int nb, int k0, int M, int tid)
{
#pragma unroll
    for (int it = 0; it < 4; it++) {
        int idx = it * 256 + tid;
        int r = idx >> 3, c = idx & 7;
        unsigned d = st + (unsigned)((r << 7) + (((c ^ (r & 7)) & 7) << 4));
        int grow = m0 + r;
        int sz = (grow < M) ? 16 : 0;
        if (grow >= M) grow = M - 1;
        size_t go = (size_t)grow * 512 + k0 + c * 8;
        cp16(d,         Ah + go, sz);
        cp16(d + 16384, Al + go, sz);
        size_t gb = (size_t)(nb + r) * 512 + k0 + c * 8;
        cp16(d + 32768, Bh + gb, 16);
        cp16(d + 49152, Bl + gb, 16);
    }
}

__global__ __launch_bounds__(256) void gemm_tc(
    const __nv_bfloat16* __restrict__ Ah, const __nv_bfloat16* __restrict__ Al,
    const __nv_bfloat16* __restrict__ Bhg, const __nv_bfloat16* __restrict__ Blg,
    float* __restrict__ C, int M, int ldc)
{
    extern __shared__ char smem[];
    const unsigned sbase = smem_u32(smem);
    const int tid = threadIdx.x, lane = tid & 31, wid = tid >> 5;
    const int m0 = blockIdx.x * 128;
    const int nb = blockIdx.y * 128;
    C += nb;
    const int wm = (wid & 3) * 32, wn = (wid >> 2) * 64;

    float acc[2][8][4];
#pragma unroll
    for (int i = 0; i < 2; i++)
#pragma unroll
        for (int j = 0; j < 8; j++)
#pragma unroll
            for (int q = 0; q < 4; q++) acc[i][j][q] = 0.f;

    load_chunk(sbase, Ah, Al, Bhg, Blg, m0, nb, 0, M, tid);
    cp_commit();

    for (int kc = 0; kc < 8; kc++) {
        if (kc < 7) {
            load_chunk(sbase + ((kc + 1) & 1) * STAGE, Ah, Al, Bhg, Blg,
                       m0, nb, (kc + 1) * KC, M, tid);
            cp_commit();
            asm volatile("cp.async.wait_group 1;" ::: "memory");
        } else {
            asm volatile("cp.async.wait_group 0;" ::: "memory");
        }
        __syncthreads();
        const unsigned st = sbase + (kc & 1) * STAGE;
#pragma unroll
        for (int kk = 0; kk < 4; kk++) {
            const int k = kk * 16;
            int ar = lane & 15;
            int ac = k + ((lane >> 4) << 3);
            unsigned ah[2][4], al[2][4];
            ldsm4(ah[0][0], ah[0][1], ah[0][2], ah[0][3], st + aoff(wm + ar, ac));
            ldsm4(ah[1][0], ah[1][1], ah[1][2], ah[1][3], st + aoff(wm + 16 + ar, ac));
            ldsm4(al[0][0], al[0][1], al[0][2], al[0][3], st + 16384 + aoff(wm + ar, ac));
            ldsm4(al[1][0], al[1][1], al[1][2], al[1][3], st + 16384 + aoff(wm + 16 + ar, ac));
            int br = (lane & 7) + ((lane >> 4) << 3);
            int bc = k + (((lane >> 3) & 1) << 3);
            unsigned bh[8][2], bl[8][2];
#pragma unroll
            for (int q = 0; q < 4; q++) {
                ldsm4(bh[2*q][0], bh[2*q][1], bh[2*q+1][0], bh[2*q+1][1],
                      st + 32768 + aoff(wn + 16 * q + br, bc));
                ldsm4(bl[2*q][0], bl[2*q][1], bl[2*q+1][0], bl[2*q+1][1],
                      st + 49152 + aoff(wn + 16 * q + br, bc));
            }
#pragma unroll
            for (int mt = 0; mt < 2; mt++)
#pragma unroll
                for (int nt = 0; nt < 8; nt++) {
                    mma16816(acc[mt][nt], ah[mt], bh[nt]);
                    mma16816(acc[mt][nt], ah[mt], bl[nt]);
                    mma16816(acc[mt][nt], al[mt], bh[nt]);
                }
        }
        __syncthreads();
    }

#pragma unroll
    for (int mt = 0; mt < 2; mt++) {
        int r0 = m0 + wm + mt * 16 + (lane >> 2);
#pragma unroll
        for (int nt = 0; nt < 8; nt++) {
            int c0 = wn + nt * 8 + (lane & 3) * 2;
            if (r0 < M)
                *(float2*)&C[(size_t)r0 * ldc + c0] =
                    make_float2(acc[mt][nt][0], acc[mt][nt][1]);
            if (r0 + 8 < M)
                *(float2*)&C[(size_t)(r0 + 8) * ldc + c0] =
                    make_float2(acc[mt][nt][2], acc[mt][nt][3]);
        }
    }
}

// ---------------- layer-1 attention scalars ----------------
__global__ __launch_bounds__(256) void scalars1_kernel(const float* __restrict__ As) {
    int n = blockIdx.x;
    int w = threadIdx.x >> 5, lane = threadIdx.x & 31;
    const float* hr = g_h_all + (size_t)n * X2DIM + w * NHID;
    float v0 = hr[lane], v1 = hr[lane + 32];
    const float* a = As + w * 2 * NHID;
    float d1 = v0 * a[lane]      + v1 * a[lane + 32];
    float d2 = v0 * a[64 + lane] + v1 * a[96 + lane];
#pragma unroll
    for (int o = 16; o; o >>= 1) {
        d1 += __shfl_down_sync(0xffffffffu, d1, o);
        d2 += __shfl_down_sync(0xffffffffu, d2, o);
    }
    if (lane == 0) { g_s1[n * 8 + w] = d1; g_s2[n * 8 + w] = d2; }
}

// ---------------- layer-1 edge aggregation (float4) + elu + bf16 split -----
__global__ __launch_bounds__(128) void agg1_kernel() {
    int n = blockIdx.x;
    int t = threadIdx.x;
    __shared__ float sh_s1[8];
    __shared__ float sh_den[8];
    __shared__ float sh_e[16 * 8];
    __shared__ int   sh_dst[16];
    if (t < 8) { sh_s1[t] = g_s1[n * 8 + t]; sh_den[t] = 0.f; }
    __syncthreads();
    int beg = g_rowptr[n], end = g_rowptr[n + 1];
    float4 acc = make_float4(0.f, 0.f, 0.f, 0.f);
    const int h = t >> 4;                  // cols 4t..4t+3 all in head t>>4
    for (int eb = beg; eb < end; eb += 16) {
        int cnt = min(16, end - eb);
        if (t < cnt) sh_dst[t] = g_col[eb + t];
        __syncthreads();
        if (t < cnt * 8) {
            int le = t >> 3, hh = t & 7;
            int d = sh_dst[le];
            float logit = sh_s1[hh] + g_s2[d * 8 + hh];
            float lr = logit > 0.f ? logit : 0.2f * logit;
            float e = __expf(-lr);
            sh_e[t] = e;
            atomicAdd(&sh_den[hh], e);
        }
        __syncthreads();
        for (int le = 0; le < cnt; le++) {
            int d = sh_dst[le];
            float w = sh_e[le * 8 + h];
            float4 v = *(const float4*)(g_h_all + (size_t)d * X2DIM + t * 4);
            acc.x += w * v.x; acc.y += w * v.y;
            acc.z += w * v.z; acc.w += w * v.w;
        }
        __syncthreads();
    }
    float inv = 1.f / sh_den[h];
    float v0 = acc.x * inv, v1 = acc.y * inv, v2 = acc.z * inv, v3 = acc.w * inv;
    v0 = v0 > 0.f ? v0 : expm1f(v0);
    v1 = v1 > 0.f ? v1 : expm1f(v1);
    v2 = v2 > 0.f ? v2 : expm1f(v2);
    v3 = v3 > 0.f ? v3 : expm1f(v3);
    __nv_bfloat16 h0 = __float2bfloat16_rn(v0);
    __nv_bfloat16 h1 = __float2bfloat16_rn(v1);
    __nv_bfloat16 h2 = __float2bfloat16_rn(v2);
    __nv_bfloat16 h3 = __float2bfloat16_rn(v3);
    __nv_bfloat16 l0 = __float2bfloat16_rn(v0 - __bfloat162float(h0));
    __nv_bfloat16 l1 = __float2bfloat16_rn(v1 - __bfloat162float(h1));
    __nv_bfloat16 l2 = __float2bfloat16_rn(v2 - __bfloat162float(h2));
    __nv_bfloat16 l3 = __float2bfloat16_rn(v3 - __bfloat162float(h3));
    size_t o = (size_t)n * X2DIM + t * 4;
    ((__nv_bfloat162*)(g_x2h + o))[0] = __nv_bfloat162(h0, h1);
    ((__nv_bfloat162*)(g_x2h + o))[1] = __nv_bfloat162(h2, h3);
    ((__nv_bfloat162*)(g_x2l + o))[0] = __nv_bfloat162(l0, l1);
    ((__nv_bfloat162*)(g_x2l + o))[1] = __nv_bfloat162(l2, l3);
}

// ---------------- layer-2 attention scalars ----------------
__global__ __launch_bounds__(128) void scalars2_kernel(
    const float* __restrict__ mua, const float* __restrict__ lva)
{
    int n = blockIdx.x, t = threadIdx.x;
    float hmu = g_hml[(size_t)n * 256 + t];
    float hlv = g_hml[(size_t)n * 256 + 128 + t];
    float p0 = hmu * mua[t];
    float p1 = hmu * mua[128 + t];
    float p2 = hlv * lva[t];
    float p3 = hlv * lva[128 + t];
#pragma unroll
    for (int o = 16; o; o >>= 1) {
        p0 += __shfl_down_sync(0xffffffffu, p0, o);
        p1 += __shfl_down_sync(0xffffffffu, p1, o);
        p2 += __shfl_down_sync(0xffffffffu, p2, o);
        p3 += __shfl_down_sync(0xffffffffu, p3, o);
    }
    __shared__ float red[4][4];
    int w = t >> 5, lane = t & 31;
    if (lane == 0) { red[w][0] = p0; red[w][1] = p1; red[w][2] = p2; red[w][3] = p3; }
    __syncthreads();
    if (t == 0) {
        g_smu1[n] = red[0][0] + red[1][0] + red[2][0] + red[3][0];
        g_smu2[n] = red[0][1] + red[1][1] + red[2][1] + red[3][1];
        g_slv1[n] = red[0][2] + red[1][2] + red[2][2] + red[3][2];
        g_slv2[n] = red[0][3] + red[1][3] + red[2][3] + red[3][3];
    }
}

// ---------------- layer-2 edge aggregation + reparameterize ----------------
__global__ __launch_bounds__(128) void agg2_kernel(
    const float* __restrict__ eps, float* __restrict__ out, int n_total)
{
    int n = blockIdx.x, t = threadIdx.x;
    __shared__ float sh_w[2][32];
    __shared__ int   sh_dst[32];
    __shared__ float sden[2];
    __shared__ float sval[256];
    if (t < 2) sden[t] = 0.f;
    float base_mu = g_smu1[n];
    float base_lv = g_slv1[n];
    __syncthreads();
    int beg = g_rowptr[n], end = g_rowptr[n + 1];
    const int sel = t >> 6;    // 0: mu cols 2t,2t+1   1: lv cols 2(t-64)..
    float2 acc = make_float2(0.f, 0.f);
    for (int eb = beg; eb < end; eb += 32) {
        int cnt = min(32, end - eb);
        if (t < cnt) {
            int d = g_col[eb + t];
            sh_dst[t] = d;
            float lmu = base_mu + g_smu2[d];
            float llv = base_lv + g_slv2[d];
            lmu = lmu > 0.f ? lmu : 0.2f * lmu;
            llv = llv > 0.f ? llv : 0.2f * llv;
            float emu = __expf(-lmu);
            float elv = __expf(-llv);
            sh_w[0][t] = emu; sh_w[1][t] = elv;
            atomicAdd(&sden[0], emu);
            atomicAdd(&sden[1], elv);
        }
        __syncthreads();
        for (int le = 0; le < cnt; le++) {
            int d = sh_dst[le];
            float w = sh_w[sel][le];
            float2 v = *(const float2*)(g_hml + (size_t)d * 256 + 2 * t);
            acc.x += w * v.x;
            acc.y += w * v.y;
        }
        __syncthreads();
    }
    float inv = 1.f / sden[sel];
    sval[2 * t]     = acc.x * inv;
    sval[2 * t + 1] = acc.y * inv;
    __syncthreads();
    float mu = sval[t];
    float lv = sval[128 + t];
    float z  = eps[(size_t)n * NOUT + t] * expf(lv) + mu;
    size_t NO = (size_t)n_total * NOUT;
    out[(size_t)n * NOUT + t]          = z;
    out[NO + (size_t)n * NOUT + t]     = mu;
    out[2 * NO + (size_t)n * NOUT + t] = lv;
}

// ---------------- host orchestration ----------------
extern "C" void kernel_launch(void* const* d_in, const int* in_sizes, int n_in,
                              void* d_out, int out_size)
{
    const float* x   = (const float*)d_in[0];
    const float* Ws  = (const float*)d_in[1];
    const float* As  = (const float*)d_in[2];
    const float* muW = (const float*)d_in[3];
    const float* mua = (const float*)d_in[4];
    const float* lvW = (const float*)d_in[5];
    const float* lva = (const float*)d_in[6];
    const float* eps = (const float*)d_in[7];
    const int*   ei  = (const int*)d_in[8];
    int E = in_sizes[8] / 2;
    int N = in_sizes[0] / NFEAT;
    float* out = (float*)d_out;

    float *p_hall, *p_hml;
    __nv_bfloat16 *p_xh, *p_xl, *p_x2h, *p_x2l;
    __nv_bfloat16 *p_bt1h, *p_bt1l, *p_bt2h, *p_bt2l;
    cudaGetSymbolAddress((void**)&p_hall, g_h_all);
    cudaGetSymbolAddress((void**)&p_hml,  g_hml);
    cudaGetSymbolAddress((void**)&p_xh,   g_xh);
    cudaGetSymbolAddress((void**)&p_xl,   g_xl);
    cudaGetSymbolAddress((void**)&p_x2h,  g_x2h);
    cudaGetSymbolAddress((void**)&p_x2l,  g_x2l);
    cudaGetSymbolAddress((void**)&p_bt1h, g_bt1h);
    cudaGetSymbolAddress((void**)&p_bt1l, g_bt1l);
    cudaGetSymbolAddress((void**)&p_bt2h, g_bt2h);
    cudaGetSymbolAddress((void**)&p_bt2l, g_bt2l);

    cudaFuncSetAttribute(gemm_tc, cudaFuncAttributeMaxDynamicSharedMemorySize, 2 * STAGE);

    // CSR keyed on src
    zero_kernel<<<(N + 255) / 256, 256>>>(N);
    hist_kernel<<<(E + 255) / 256, 256>>>(ei, E);
    scan_kernel<<<1, 1024>>>(N);
    fill_kernel<<<(E + 255) / 256, 256>>>(ei, E);

    // operand conversion
    convert_x_kernel<<<(N * NFEAT / 4 + 255) / 256, 256>>>(x, N * NFEAT / 4);
    convert_w_kernel<<<(512 * 512 + 256 * 512 + 255) / 256, 256>>>(Ws, muW, lvW);

    int mtiles = (N + 127) / 128;
    // layer-1: C = g_h_all [N,512]
    gemm_tc<<<dim3(mtiles, 4), 256, 2 * STAGE>>>(p_xh, p_xl, p_bt1h, p_bt1l,
                                                 p_hall, N, X2DIM);
    scalars1_kernel<<<N, 256>>>(As);
    agg1_kernel<<<N, 128>>>();

    // layer-2: fused mu|lv GEMM, C = g_hml [N,256]
    gemm_tc<<<dim3(mtiles, 2), 256, 2 * STAGE>>>(p_x2h, p_x2l, p_bt2h, p_bt2l,
                                                 p_hml, N, 256);
    scalars2_kernel<<<N, 128>>>(mua, lva);
    agg2_kernel<<<N, 128>>>(eps, out, N);
}